// round 16
// baseline (speedup 1.0000x reference)
#include <cuda_runtime.h>
#include <cuda_bf16.h>
#include <cstdint>

// Problem dims (fixed by dataset)
#define M_TOK   512
#define N_DIM   2048
#define D_HEAD  128
#define H_HEADS 16
#define L_CACHE 4096
#define N3      6144   // 3*N_DIM

// -------- device scratch (no allocations allowed) --------
__device__ float g_q[H_HEADS * M_TOK * D_HEAD];   // [H][M][D] (raw, un-normalized)
__device__ float g_k[H_HEADS * M_TOK * D_HEAD];   // raw
__device__ float g_v[H_HEADS * M_TOK * D_HEAD];
__device__ float g_po[2 * H_HEADS * M_TOK * D_HEAD]; // partial numerators per L-split
__device__ float g_pd[2 * H_HEADS * M_TOK];           // partial denominators

// bf16x3 split operands for warp-MMA QKV GEMM
__device__ __nv_bfloat16 g_xhi[M_TOK * N_DIM];        // X  [m][k]
__device__ __nv_bfloat16 g_xlo[M_TOK * N_DIM];
__device__ __nv_bfloat16 g_wthi[(size_t)N3 * N_DIM];  // W^T [n][k]
__device__ __nv_bfloat16 g_wtlo[(size_t)N3 * N_DIM];

// pre-split, scatter-updated, K-normalized KV cache [H][L][D]
__device__ __nv_bfloat16 g_kchi[(size_t)H_HEADS * L_CACHE * D_HEAD];
__device__ __nv_bfloat16 g_kclo[(size_t)H_HEADS * L_CACHE * D_HEAD];
__device__ __nv_bfloat16 g_vchi[(size_t)H_HEADS * L_CACHE * D_HEAD];
__device__ __nv_bfloat16 g_vclo[(size_t)H_HEADS * L_CACHE * D_HEAD];

// ============================================================
// helpers
// ============================================================
__device__ __forceinline__ uint32_t smem_u32(const void* p) {
    uint32_t a;
    asm("{ .reg .u64 t; cvta.to.shared.u64 t, %1; cvt.u32.u64 %0, t; }"
        : "=r"(a) : "l"(p));
    return a;
}

__device__ __forceinline__ void ldm_x4(uint32_t& d0, uint32_t& d1,
                                       uint32_t& d2, uint32_t& d3, uint32_t addr) {
    asm volatile("ldmatrix.sync.aligned.m8n8.x4.shared.b16 {%0,%1,%2,%3}, [%4];"
                 : "=r"(d0), "=r"(d1), "=r"(d2), "=r"(d3) : "r"(addr));
}

__device__ __forceinline__ void ldm_x4_t(uint32_t& d0, uint32_t& d1,
                                         uint32_t& d2, uint32_t& d3, uint32_t addr) {
    asm volatile("ldmatrix.sync.aligned.m8n8.x4.trans.shared.b16 {%0,%1,%2,%3}, [%4];"
                 : "=r"(d0), "=r"(d1), "=r"(d2), "=r"(d3) : "r"(addr));
}

__device__ __forceinline__ void mma16816(float* c, const uint32_t* a, const uint32_t* b) {
    asm volatile(
        "mma.sync.aligned.m16n8k16.row.col.f32.bf16.bf16.f32 "
        "{%0,%1,%2,%3}, {%4,%5,%6,%7}, {%8,%9}, {%0,%1,%2,%3};"
        : "+f"(c[0]), "+f"(c[1]), "+f"(c[2]), "+f"(c[3])
        : "r"(a[0]), "r"(a[1]), "r"(a[2]), "r"(a[3]), "r"(b[0]), "r"(b[1]));
}

__device__ __forceinline__ void cp_async16(uint32_t dst, const void* src) {
    asm volatile("cp.async.cg.shared.global [%0], [%1], 16;" :: "r"(dst), "l"(src));
}
#define CP_COMMIT() asm volatile("cp.async.commit_group;" ::: "memory")
#define CP_WAIT0()  asm volatile("cp.async.wait_group 0;" ::: "memory")

__device__ __forceinline__ void split_bf16(float x, __nv_bfloat16& hi, __nv_bfloat16& lo) {
    hi = __float2bfloat16_rn(x);
    lo = __float2bfloat16_rn(x - __bfloat162float(hi));
}

__device__ __forceinline__ uint32_t pack2(__nv_bfloat16 a, __nv_bfloat16 b) {
    return (uint32_t)__bfloat16_as_ushort(a) | ((uint32_t)__bfloat16_as_ushort(b) << 16);
}

// ============================================================
// Kernel 0: fused convert_x + convert_w (flat grid partition)
// ============================================================
#define XW_XBLOCKS 1024   // (512*2048/4)/256

__global__ __launch_bounds__(256) void convert_xw_kernel(
    const float* __restrict__ X, const float* __restrict__ W)
{
    if (blockIdx.x < XW_XBLOCKS) {
        int idx = blockIdx.x * 256 + threadIdx.x;
        float4 v = *(const float4*)(X + idx * 4);
        __nv_bfloat16 h0, l0, h1, l1, h2, l2, h3, l3;
        split_bf16(v.x, h0, l0); split_bf16(v.y, h1, l1);
        split_bf16(v.z, h2, l2); split_bf16(v.w, h3, l3);
        __nv_bfloat162* ph = (__nv_bfloat162*)(g_xhi + idx * 4);
        __nv_bfloat162* pl = (__nv_bfloat162*)(g_xlo + idx * 4);
        ph[0] = __nv_bfloat162(h0, h1); ph[1] = __nv_bfloat162(h2, h3);
        pl[0] = __nv_bfloat162(l0, l1); pl[1] = __nv_bfloat162(l2, l3);
        return;
    }

    __shared__ float tile[32][33];
    int bw = blockIdx.x - XW_XBLOCKS;           // 0..12287
    const int n0 = (bw % (N3 / 32)) * 32;
    const int k0 = (bw / (N3 / 32)) * 32;
    const int tx = threadIdx.x & 31;
    const int ty = threadIdx.x >> 5;

    #pragma unroll
    for (int l = 0; l < 4; ++l)
        tile[ty * 4 + l][tx] = W[(size_t)(k0 + ty * 4 + l) * N3 + n0 + tx];
    __syncthreads();

    #pragma unroll
    for (int l = 0; l < 4; ++l) {
        int nl = ty * 4 + l;
        float x = tile[tx][nl];
        __nv_bfloat16 hi, lo;
        split_bf16(x, hi, lo);
        size_t o = (size_t)(n0 + nl) * N_DIM + k0 + tx;
        g_wthi[o] = hi;
        g_wtlo[o] = lo;
    }
}

// ============================================================
// Kernel 1: QKV GEMM via mma.sync bf16x3 (R10 v1 config)
// BM=128, BN=64, BK=32; 256 thr = 8 warps (4x2), warp tile 32x32.
// ============================================================
#define PITCH_B   80
#define A_TILE_B  (128 * PITCH_B)   // 10240
#define B_TILE_B  (64  * PITCH_B)   // 5120
#define OFF_AHI   0
#define OFF_ALO   A_TILE_B
#define OFF_BHI   (2 * A_TILE_B)
#define OFF_BLO   (2 * A_TILE_B + B_TILE_B)
#define BUF_B     (2 * A_TILE_B + 2 * B_TILE_B)   // 30720
#define GEMM_SMEM (2 * BUF_B)                     // 61440

__global__ __launch_bounds__(256) void qkv_mma_kernel()
{
    extern __shared__ __align__(128) char sm[];
    const uint32_t sb = smem_u32(sm);
    const int t    = threadIdx.x;
    const int lane = t & 31;
    const int wid  = t >> 5;
    const int wm   = wid & 3;        // 0..3  (m-warp)
    const int wn   = wid >> 2;       // 0..1  (n-warp)
    const int lg   = lane >> 3;      // ldmatrix group 0..3
    const int lr   = lane & 7;
    const int m0   = blockIdx.y * 128;
    const int n0   = blockIdx.x * 64;

    auto load_tiles = [&](int k0, int buf) {
        char* base = sm + buf * BUF_B;
        #pragma unroll
        for (int i = 0; i < 6; ++i) {
            int idx = t + i * 256;                 // 0..1535 16B chunks
            const __nv_bfloat16* gsrc;
            int local, off;
            if (idx < 512)       { gsrc = g_xhi  + (size_t)m0 * N_DIM; local = idx;        off = OFF_AHI; }
            else if (idx < 1024) { gsrc = g_xlo  + (size_t)m0 * N_DIM; local = idx - 512;  off = OFF_ALO; }
            else if (idx < 1280) { gsrc = g_wthi + (size_t)n0 * N_DIM; local = idx - 1024; off = OFF_BHI; }
            else                 { gsrc = g_wtlo + (size_t)n0 * N_DIM; local = idx - 1280; off = OFF_BLO; }
            int r = local >> 2, c = local & 3;
            uint4 v = *(const uint4*)(gsrc + (size_t)r * N_DIM + k0 + c * 8);
            *(uint4*)(base + off + r * PITCH_B + c * 16) = v;
        }
    };

    float acc[2][4][4];
    #pragma unroll
    for (int mi = 0; mi < 2; ++mi)
        #pragma unroll
        for (int nf = 0; nf < 4; ++nf)
            #pragma unroll
            for (int e = 0; e < 4; ++e) acc[mi][nf][e] = 0.f;

    load_tiles(0, 0);

    const int NIT = N_DIM / 32;    // 64
    for (int it = 0; it < NIT; ++it) {
        const int buf = it & 1;
        __syncthreads();
        if (it + 1 < NIT) load_tiles((it + 1) * 32, buf ^ 1);

        const uint32_t bb = sb + buf * BUF_B;
        #pragma unroll
        for (int ks = 0; ks < 2; ++ks) {
            uint32_t aHi[2][4], aLo[2][4], bHi[4][2], bLo[4][2];
            #pragma unroll
            for (int mi = 0; mi < 2; ++mi) {
                int row = wm * 32 + mi * 16 + lr + (lg & 1) * 8;
                int col = ks * 16 + (lg >> 1) * 8;
                uint32_t ad = bb + OFF_AHI + row * PITCH_B + col * 2;
                ldm_x4(aHi[mi][0], aHi[mi][1], aHi[mi][2], aHi[mi][3], ad);
                ldm_x4(aLo[mi][0], aLo[mi][1], aLo[mi][2], aLo[mi][3], ad + (OFF_ALO - OFF_AHI));
            }
            #pragma unroll
            for (int nj = 0; nj < 2; ++nj) {
                int row = wn * 32 + nj * 16 + (lg >> 1) * 8 + lr;
                int col = ks * 16 + (lg & 1) * 8;
                uint32_t bd = bb + OFF_BHI + row * PITCH_B + col * 2;
                uint32_t d0, d1, d2, d3;
                ldm_x4(d0, d1, d2, d3, bd);
                bHi[nj * 2][0] = d0; bHi[nj * 2][1] = d1;
                bHi[nj * 2 + 1][0] = d2; bHi[nj * 2 + 1][1] = d3;
                ldm_x4(d0, d1, d2, d3, bd + (OFF_BLO - OFF_BHI));
                bLo[nj * 2][0] = d0; bLo[nj * 2][1] = d1;
                bLo[nj * 2 + 1][0] = d2; bLo[nj * 2 + 1][1] = d3;
            }
            #pragma unroll
            for (int mi = 0; mi < 2; ++mi)
                #pragma unroll
                for (int nf = 0; nf < 4; ++nf) {
                    mma16816(acc[mi][nf], aHi[mi], bHi[nf]);
                    mma16816(acc[mi][nf], aHi[mi], bLo[nf]);
                    mma16816(acc[mi][nf], aLo[mi], bHi[nf]);
                }
        }
    }

    const int part  = n0 >> 11;
    const int h     = (n0 >> 7) & 15;
    const int dbase = n0 & 64;
    float* dstp = (part == 0 ? g_q : (part == 1 ? g_k : g_v))
                  + (size_t)h * (M_TOK * D_HEAD);

    #pragma unroll
    for (int mi = 0; mi < 2; ++mi)
        #pragma unroll
        for (int nf = 0; nf < 4; ++nf) {
            int row = m0 + wm * 32 + mi * 16 + (lane >> 2);
            int col = dbase + wn * 32 + nf * 8 + (lane & 3) * 2;
            *(float2*)(dstp + (size_t)row * D_HEAD + col) =
                make_float2(acc[mi][nf][0], acc[mi][nf][1]);
            *(float2*)(dstp + (size_t)(row + 8) * D_HEAD + col) =
                make_float2(acc[mi][nf][2], acc[mi][nf][3]);
        }
}

// ============================================================
// Kernel 2: build pre-split scatter-updated KV cache.
// Fresh K rows get fused RMS norm (one warp covers one 128-elem row).
// ============================================================
__global__ __launch_bounds__(256) void convert_kv_kernel(
    const float* __restrict__ cK, const float* __restrict__ cV,
    const int* __restrict__ Pp)
{
    const int P = Pp[0];
    int idx = blockIdx.x * 256 + threadIdx.x;      // float4 index over H*L*D
    int e = idx * 4;
    int d = e & 127;
    int l = (e >> 7) & (L_CACHE - 1);
    int h = e >> 19;
    size_t o = (size_t)h * (L_CACHE * D_HEAD) + (size_t)l * D_HEAD + d;
    bool fresh = (l >= P && l < P + M_TOK);        // warp-uniform (row-aligned)
    size_t of = ((size_t)h * M_TOK + (l - P)) * D_HEAD + d;

    float4 kv = fresh ? *(const float4*)(g_k + of) : *(const float4*)(cK + o);
    if (fresh) {
        float ss = kv.x * kv.x + kv.y * kv.y + kv.z * kv.z + kv.w * kv.w;
        #pragma unroll
        for (int off = 16; off > 0; off >>= 1)
            ss += __shfl_xor_sync(0xffffffffu, ss, off);
        float sc = rsqrtf(ss * (1.0f / 128.0f));
        kv.x *= sc; kv.y *= sc; kv.z *= sc; kv.w *= sc;
    }
    __nv_bfloat16 a0, b0, a1, b1, a2, b2, a3, b3;
    split_bf16(kv.x, a0, b0); split_bf16(kv.y, a1, b1);
    split_bf16(kv.z, a2, b2); split_bf16(kv.w, a3, b3);
    *(uint2*)(g_kchi + o) = make_uint2(pack2(a0, a1), pack2(a2, a3));
    *(uint2*)(g_kclo + o) = make_uint2(pack2(b0, b1), pack2(b2, b3));

    kv = fresh ? *(const float4*)(g_v + of) : *(const float4*)(cV + o);
    split_bf16(kv.x, a0, b0); split_bf16(kv.y, a1, b1);
    split_bf16(kv.z, a2, b2); split_bf16(kv.w, a3, b3);
    *(uint2*)(g_vchi + o) = make_uint2(pack2(a0, a1), pack2(a2, a3));
    *(uint2*)(g_vclo + o) = make_uint2(pack2(b0, b1), pack2(b2, b3));
}

// ============================================================
// Kernel 3: full-tensor attention, 2 CTAs/SM for phase overlap.
// CTA = 128 threads = 4 warps; warp owns 16 m-rows, full CL=32 l,
// full d=128. m-tile 64. grid (8, 16, 2). smem ~102 KB -> occ 2.
// Register-P, cp.async double buffer, fused q RMS norm.
// ============================================================
#define CL        32
#define QROWS     64
#define QP_B      272                        // 128 bf16 + 8 pad
#define Q_HI_OFF  0
#define Q_LO_OFF  (QROWS * QP_B)             // 17408
#define BUF0_OFF  (2 * QROWS * QP_B)         // 34816
#define KB_KHI    0
#define KB_KLO    (CL * QP_B)                // 8704
#define KB_VHI    (2 * CL * QP_B)            // 17408
#define KB_VLO    (3 * CL * QP_B)            // 26112
#define KVBUF_B   (4 * CL * QP_B)            // 34816
#define ATTN_SMEM_B (BUF0_OFF + 2 * KVBUF_B) // 104448

__global__ __launch_bounds__(128, 2) void attn_kernel()
{
    extern __shared__ __align__(128) char sm[];
    const uint32_t sb = smem_u32(sm);

    const int t    = threadIdx.x;
    const int lane = t & 31;
    const int wid  = t >> 5;      // m-warp 0..3: rows wid*16..+16
    const int lr   = lane & 7;
    const int lg   = lane >> 3;
    const int h    = blockIdx.y;
    const int m0   = blockIdx.x * 64;
    const int z    = blockIdx.z;

    // ---- load Q tile (64 rows) with fused RMS norm (warp = row), split hi/lo ----
    const float* qbase = g_q + (h * M_TOK + m0) * D_HEAD;
    #pragma unroll
    for (int i = 0; i < 16; ++i) {
        int idx = t + i * 128;         // 0..2047 float4
        int row = idx >> 5;            // warp-uniform
        int c4  = idx & 31;            // = lane
        float4 v = *(const float4*)(qbase + row * 128 + c4 * 4);
        float ss = v.x * v.x + v.y * v.y + v.z * v.z + v.w * v.w;
        #pragma unroll
        for (int off = 16; off > 0; off >>= 1)
            ss += __shfl_xor_sync(0xffffffffu, ss, off);
        float sc = rsqrtf(ss * (1.0f / 128.0f));
        v.x *= sc; v.y *= sc; v.z *= sc; v.w *= sc;
        __nv_bfloat16 h0, l0, h1, l1, h2, l2, h3, l3;
        split_bf16(v.x, h0, l0); split_bf16(v.y, h1, l1);
        split_bf16(v.z, h2, l2); split_bf16(v.w, h3, l3);
        *(uint2*)(sm + Q_HI_OFF + row * QP_B + c4 * 8) = make_uint2(pack2(h0, h1), pack2(h2, h3));
        *(uint2*)(sm + Q_LO_OFF + row * QP_B + c4 * 8) = make_uint2(pack2(l0, l1), pack2(l2, l3));
    }

    const size_t hoff = (size_t)h * (L_CACHE * D_HEAD);

    auto load_chunk = [&](int ch, int buf) {
        const int l0g = z * 2048 + ch * CL;
        const char* srcs[4] = {
            (const char*)(g_kchi + hoff + (size_t)l0g * D_HEAD),
            (const char*)(g_kclo + hoff + (size_t)l0g * D_HEAD),
            (const char*)(g_vchi + hoff + (size_t)l0g * D_HEAD),
            (const char*)(g_vclo + hoff + (size_t)l0g * D_HEAD)
        };
        const uint32_t bo = sb + BUF0_OFF + buf * KVBUF_B;
        #pragma unroll
        for (int i = 0; i < 16; ++i) {
            int idx   = t + i * 128;      // 0..2047 16B chunks
            int a     = idx >> 9;         // array 0..3 (512 chunks each)
            int local = idx & 511;
            int row   = local >> 4;       // 0..31
            int c     = local & 15;
            cp_async16(bo + a * (CL * QP_B) + row * QP_B + c * 16,
                       srcs[a] + row * 256 + c * 16);
        }
    };

    // out accumulators: 16m x 128d per warp = 16(nd) x 4 = 64 regs
    float out_acc[16][4];
    #pragma unroll
    for (int nd = 0; nd < 16; ++nd)
        #pragma unroll
        for (int e = 0; e < 4; ++e) out_acc[nd][e] = 0.f;
    float den_acc[2] = {0.f, 0.f};

    load_chunk(0, 0);
    CP_COMMIT();
    CP_WAIT0();
    __syncthreads();

    const int NCH = 2048 / CL;   // 64
    for (int ch = 0; ch < NCH; ++ch) {
        const int buf = ch & 1;
        const uint32_t bo = sb + BUF0_OFF + buf * KVBUF_B;
        if (ch + 1 < NCH) { load_chunk(ch + 1, buf ^ 1); CP_COMMIT(); }

        // ---- S = Q K^T (warp: 16m x full 32l) -> s[4][4] ----
        float s[4][4];
        #pragma unroll
        for (int nj = 0; nj < 4; ++nj)
            #pragma unroll
            for (int e = 0; e < 4; ++e) s[nj][e] = 0.f;

        #pragma unroll
        for (int ks = 0; ks < 8; ++ks) {
            uint32_t aHi[4], aLo[4];
            {
                int row = wid * 16 + lr + (lg & 1) * 8;
                uint32_t ad = sb + Q_HI_OFF + row * QP_B + ks * 32 + (lg >> 1) * 16;
                ldm_x4(aHi[0], aHi[1], aHi[2], aHi[3], ad);
                ldm_x4(aLo[0], aLo[1], aLo[2], aLo[3], ad + Q_LO_OFF);
            }
            #pragma unroll
            for (int ng = 0; ng < 2; ++ng) {
                int row = ng * 16 + (lg >> 1) * 8 + lr;
                uint32_t bd = bo + KB_KHI + row * QP_B + ks * 32 + (lg & 1) * 16;
                uint32_t d0, d1, d2, d3, e0, e1, e2, e3;
                ldm_x4(d0, d1, d2, d3, bd);
                ldm_x4(e0, e1, e2, e3, bd + (KB_KLO - KB_KHI));
                uint32_t bh0[2] = {d0, d1}, bh1[2] = {d2, d3};
                uint32_t bl0[2] = {e0, e1}, bl1[2] = {e2, e3};
                mma16816(s[ng * 2],     aHi, bh0);
                mma16816(s[ng * 2],     aHi, bl0);
                mma16816(s[ng * 2],     aLo, bh0);
                mma16816(s[ng * 2 + 1], aHi, bh1);
                mma16816(s[ng * 2 + 1], aHi, bl1);
                mma16816(s[ng * 2 + 1], aLo, bh1);
            }
        }

        // ---- exp + den accumulation (registers only) ----
        {
            float sa = 0.f, sbv = 0.f;
            #pragma unroll
            for (int nj = 0; nj < 4; ++nj) {
                s[nj][0] = __expf(s[nj][0]);
                s[nj][1] = __expf(s[nj][1]);
                s[nj][2] = __expf(s[nj][2]);
                s[nj][3] = __expf(s[nj][3]);
                sa  += s[nj][0] + s[nj][1];
                sbv += s[nj][2] + s[nj][3];
            }
            den_acc[0] += sa;
            den_acc[1] += sbv;
        }

        // ---- repack S C-frags into PV A-frags (hi/lo), registers only ----
        uint32_t aPhi[2][4], aPlo[2][4];
        #pragma unroll
        for (int kp = 0; kp < 2; ++kp)
            #pragma unroll
            for (int half = 0; half < 2; ++half) {
                const float* sv = s[2 * kp + half];
                __nv_bfloat16 h0, l0b, h1, l1b;
                split_bf16(sv[0], h0, l0b); split_bf16(sv[1], h1, l1b);
                aPhi[kp][half * 2]     = pack2(h0, h1);
                aPlo[kp][half * 2]     = pack2(l0b, l1b);
                split_bf16(sv[2], h0, l0b); split_bf16(sv[3], h1, l1b);
                aPhi[kp][half * 2 + 1] = pack2(h0, h1);
                aPlo[kp][half * 2 + 1] = pack2(l0b, l1b);
            }

        // ---- out += P V (full 32l x 128d) ----
        #pragma unroll
        for (int kp = 0; kp < 2; ++kp) {
            #pragma unroll
            for (int g = 0; g < 8; ++g) {
                int vrow = kp * 16 + (lg & 1) * 8 + lr;
                int vcol = g * 16 + (lg >> 1) * 8;
                uint32_t bd = bo + KB_VHI + vrow * QP_B + vcol * 2;
                uint32_t d0, d1, d2, d3, e0, e1, e2, e3;
                ldm_x4_t(d0, d1, d2, d3, bd);
                ldm_x4_t(e0, e1, e2, e3, bd + (KB_VLO - KB_VHI));
                uint32_t bh0[2] = {d0, d1}, bh1[2] = {d2, d3};
                uint32_t bl0[2] = {e0, e1}, bl1[2] = {e2, e3};
                mma16816(out_acc[2 * g],     aPhi[kp], bh0);
                mma16816(out_acc[2 * g],     aPhi[kp], bl0);
                mma16816(out_acc[2 * g],     aPlo[kp], bh0);
                mma16816(out_acc[2 * g + 1], aPhi[kp], bh1);
                mma16816(out_acc[2 * g + 1], aPhi[kp], bl1);
                mma16816(out_acc[2 * g + 1], aPlo[kp], bh1);
            }
        }

        CP_WAIT0();
        __syncthreads();
    }

    // ---- denominator: shfl reduce, direct write (warp owns its 16 rows) ----
    float* pd = g_pd + (z * H_HEADS + h) * M_TOK + m0;
    #pragma unroll
    for (int half = 0; half < 2; ++half) {
        float v = den_acc[half];
        v += __shfl_xor_sync(0xffffffffu, v, 1);
        v += __shfl_xor_sync(0xffffffffu, v, 2);
        if ((lane & 3) == 0)
            pd[wid * 16 + half * 8 + (lane >> 2)] = v;
    }

    // ---- direct output write ----
    float* po = g_po + ((size_t)(z * H_HEADS + h) * M_TOK + m0) * D_HEAD;
    #pragma unroll
    for (int nd = 0; nd < 16; ++nd) {
        int row = wid * 16 + (lane >> 2);
        int col = nd * 8 + (lane & 3) * 2;
        *(float2*)(po + (size_t)row * D_HEAD + col) =
            make_float2(out_acc[nd][0], out_acc[nd][1]);
        *(float2*)(po + (size_t)(row + 8) * D_HEAD + col) =
            make_float2(out_acc[nd][2], out_acc[nd][3]);
    }
}

// ============================================================
// Kernel 4: combine L-splits and write output [M, H*D]
// ============================================================
__global__ __launch_bounds__(256) void combine_kernel(float* __restrict__ out)
{
    int idx = blockIdx.x * 256 + threadIdx.x;
    int e = idx * 4;
    int d = e & 127;
    int m = (e >> 7) & 511;
    int h = e >> 16;

    float4 a = *(const float4*)(g_po + e);
    float4 b = *(const float4*)(g_po + H_HEADS * M_TOK * D_HEAD + e);
    float dn = g_pd[h * M_TOK + m] + g_pd[H_HEADS * M_TOK + h * M_TOK + m];
    float inv = 1.0f / dn;
    float4 r = make_float4((a.x + b.x) * inv, (a.y + b.y) * inv,
                           (a.z + b.z) * inv, (a.w + b.w) * inv);
    *(float4*)(out + m * N_DIM + h * D_HEAD + d) = r;
}

// ============================================================
extern "C" void kernel_launch(void* const* d_in, const int* in_sizes, int n_in,
                              void* d_out, int out_size)
{
    const float* X  = (const float*)d_in[0];
    const float* W  = (const float*)d_in[1];
    const float* cK = (const float*)d_in[2];
    const float* cV = (const float*)d_in[3];
    const int*   Pp = (const int*)d_in[4];
    float* out = (float*)d_out;

    cudaFuncSetAttribute(attn_kernel,
                         cudaFuncAttributeMaxDynamicSharedMemorySize, ATTN_SMEM_B);
    cudaFuncSetAttribute(qkv_mma_kernel,
                         cudaFuncAttributeMaxDynamicSharedMemorySize, GEMM_SMEM);

    convert_xw_kernel<<<XW_XBLOCKS + (N3 / 32) * (N_DIM / 32), 256>>>(X, W);
    qkv_mma_kernel<<<dim3(N3 / 64, M_TOK / 128), 256, GEMM_SMEM>>>();
    convert_kv_kernel<<<(H_HEADS * L_CACHE * D_HEAD / 4) / 256, 256>>>(cK, cV, Pp);
    attn_kernel<<<dim3(M_TOK / 64, H_HEADS, 2), 128, ATTN_SMEM_B>>>();
    combine_kernel<<<(H_HEADS * M_TOK * D_HEAD / 4) / 256, 256>>>(out);
}

// round 17
// speedup vs baseline: 1.6256x; 1.6256x over previous
#include <cuda_runtime.h>
#include <cuda_bf16.h>
#include <cstdint>

// Problem dims (fixed by dataset)
#define M_TOK   512
#define N_DIM   2048
#define D_HEAD  128
#define H_HEADS 16
#define L_CACHE 4096
#define N3      6144   // 3*N_DIM

// -------- device scratch (no allocations allowed) --------
__device__ float g_q[H_HEADS * M_TOK * D_HEAD];   // [H][M][D] (raw, un-normalized)
__device__ float g_k[H_HEADS * M_TOK * D_HEAD];   // raw
__device__ float g_v[H_HEADS * M_TOK * D_HEAD];
__device__ float g_po[2 * H_HEADS * M_TOK * D_HEAD]; // partial numerators per L-split
__device__ float g_pd[2 * H_HEADS * M_TOK];           // partial denominators

// bf16x3 split operands for warp-MMA QKV GEMM
__device__ __nv_bfloat16 g_xhi[M_TOK * N_DIM];        // X  [m][k]
__device__ __nv_bfloat16 g_xlo[M_TOK * N_DIM];
__device__ __nv_bfloat16 g_wthi[(size_t)N3 * N_DIM];  // W^T [n][k]
__device__ __nv_bfloat16 g_wtlo[(size_t)N3 * N_DIM];

// pre-split, scatter-updated, K-normalized KV cache [H][L][D]
__device__ __nv_bfloat16 g_kchi[(size_t)H_HEADS * L_CACHE * D_HEAD];
__device__ __nv_bfloat16 g_kclo[(size_t)H_HEADS * L_CACHE * D_HEAD];
__device__ __nv_bfloat16 g_vchi[(size_t)H_HEADS * L_CACHE * D_HEAD];
__device__ __nv_bfloat16 g_vclo[(size_t)H_HEADS * L_CACHE * D_HEAD];

// ============================================================
// helpers
// ============================================================
__device__ __forceinline__ uint32_t smem_u32(const void* p) {
    uint32_t a;
    asm("{ .reg .u64 t; cvta.to.shared.u64 t, %1; cvt.u32.u64 %0, t; }"
        : "=r"(a) : "l"(p));
    return a;
}

__device__ __forceinline__ void ldm_x4(uint32_t& d0, uint32_t& d1,
                                       uint32_t& d2, uint32_t& d3, uint32_t addr) {
    asm volatile("ldmatrix.sync.aligned.m8n8.x4.shared.b16 {%0,%1,%2,%3}, [%4];"
                 : "=r"(d0), "=r"(d1), "=r"(d2), "=r"(d3) : "r"(addr));
}

__device__ __forceinline__ void ldm_x4_t(uint32_t& d0, uint32_t& d1,
                                         uint32_t& d2, uint32_t& d3, uint32_t addr) {
    asm volatile("ldmatrix.sync.aligned.m8n8.x4.trans.shared.b16 {%0,%1,%2,%3}, [%4];"
                 : "=r"(d0), "=r"(d1), "=r"(d2), "=r"(d3) : "r"(addr));
}

__device__ __forceinline__ void mma16816(float* c, const uint32_t* a, const uint32_t* b) {
    asm volatile(
        "mma.sync.aligned.m16n8k16.row.col.f32.bf16.bf16.f32 "
        "{%0,%1,%2,%3}, {%4,%5,%6,%7}, {%8,%9}, {%0,%1,%2,%3};"
        : "+f"(c[0]), "+f"(c[1]), "+f"(c[2]), "+f"(c[3])
        : "r"(a[0]), "r"(a[1]), "r"(a[2]), "r"(a[3]), "r"(b[0]), "r"(b[1]));
}

__device__ __forceinline__ void cp_async16(uint32_t dst, const void* src) {
    asm volatile("cp.async.cg.shared.global [%0], [%1], 16;" :: "r"(dst), "l"(src));
}
#define CP_COMMIT() asm volatile("cp.async.commit_group;" ::: "memory")
#define CP_WAIT0()  asm volatile("cp.async.wait_group 0;" ::: "memory")

__device__ __forceinline__ void split_bf16(float x, __nv_bfloat16& hi, __nv_bfloat16& lo) {
    hi = __float2bfloat16_rn(x);
    lo = __float2bfloat16_rn(x - __bfloat162float(hi));
}

__device__ __forceinline__ uint32_t pack2(__nv_bfloat16 a, __nv_bfloat16 b) {
    return (uint32_t)__bfloat16_as_ushort(a) | ((uint32_t)__bfloat16_as_ushort(b) << 16);
}

// ============================================================
// Kernel 0: fused convert_x + convert_w (flat grid partition)
// ============================================================
#define XW_XBLOCKS 1024   // (512*2048/4)/256

__global__ __launch_bounds__(256) void convert_xw_kernel(
    const float* __restrict__ X, const float* __restrict__ W)
{
    if (blockIdx.x < XW_XBLOCKS) {
        int idx = blockIdx.x * 256 + threadIdx.x;
        float4 v = *(const float4*)(X + idx * 4);
        __nv_bfloat16 h0, l0, h1, l1, h2, l2, h3, l3;
        split_bf16(v.x, h0, l0); split_bf16(v.y, h1, l1);
        split_bf16(v.z, h2, l2); split_bf16(v.w, h3, l3);
        __nv_bfloat162* ph = (__nv_bfloat162*)(g_xhi + idx * 4);
        __nv_bfloat162* pl = (__nv_bfloat162*)(g_xlo + idx * 4);
        ph[0] = __nv_bfloat162(h0, h1); ph[1] = __nv_bfloat162(h2, h3);
        pl[0] = __nv_bfloat162(l0, l1); pl[1] = __nv_bfloat162(l2, l3);
        return;
    }

    __shared__ float tile[32][33];
    int bw = blockIdx.x - XW_XBLOCKS;           // 0..12287
    const int n0 = (bw % (N3 / 32)) * 32;
    const int k0 = (bw / (N3 / 32)) * 32;
    const int tx = threadIdx.x & 31;
    const int ty = threadIdx.x >> 5;

    #pragma unroll
    for (int l = 0; l < 4; ++l)
        tile[ty * 4 + l][tx] = W[(size_t)(k0 + ty * 4 + l) * N3 + n0 + tx];
    __syncthreads();

    #pragma unroll
    for (int l = 0; l < 4; ++l) {
        int nl = ty * 4 + l;
        float x = tile[tx][nl];
        __nv_bfloat16 hi, lo;
        split_bf16(x, hi, lo);
        size_t o = (size_t)(n0 + nl) * N_DIM + k0 + tx;
        g_wthi[o] = hi;
        g_wtlo[o] = lo;
    }
}

// ============================================================
// Kernel 1: QKV GEMM via mma.sync bf16x3, cp.async double buffer.
// BM=128, BN=64, BK=32; 256 thr = 8 warps (4x2), warp tile 32x32.
// smem 61 KB -> 2 CTAs/SM.
// ============================================================
#define PITCH_B   80
#define A_TILE_B  (128 * PITCH_B)   // 10240
#define B_TILE_B  (64  * PITCH_B)   // 5120
#define OFF_AHI   0
#define OFF_ALO   A_TILE_B
#define OFF_BHI   (2 * A_TILE_B)
#define OFF_BLO   (2 * A_TILE_B + B_TILE_B)
#define BUF_B     (2 * A_TILE_B + 2 * B_TILE_B)   // 30720
#define GEMM_SMEM (2 * BUF_B)                     // 61440

__global__ __launch_bounds__(256, 2) void qkv_mma_kernel()
{
    extern __shared__ __align__(128) char sm[];
    const uint32_t sb = smem_u32(sm);
    const int t    = threadIdx.x;
    const int lane = t & 31;
    const int wid  = t >> 5;
    const int wm   = wid & 3;        // 0..3  (m-warp)
    const int wn   = wid >> 2;       // 0..1  (n-warp)
    const int lg   = lane >> 3;      // ldmatrix group 0..3
    const int lr   = lane & 7;
    const int m0   = blockIdx.y * 128;
    const int n0   = blockIdx.x * 64;

    // cp.async loader: 1536 16B chunks (Ahi 512, Alo 512, Bhi 256, Blo 256)
    auto load_tiles = [&](int k0, int buf) {
        const uint32_t bo = sb + buf * BUF_B;
        #pragma unroll
        for (int i = 0; i < 6; ++i) {
            int idx = t + i * 256;                 // 0..1535
            const __nv_bfloat16* gsrc;
            int local, off;
            if (idx < 512)       { gsrc = g_xhi  + (size_t)m0 * N_DIM; local = idx;        off = OFF_AHI; }
            else if (idx < 1024) { gsrc = g_xlo  + (size_t)m0 * N_DIM; local = idx - 512;  off = OFF_ALO; }
            else if (idx < 1280) { gsrc = g_wthi + (size_t)n0 * N_DIM; local = idx - 1024; off = OFF_BHI; }
            else                 { gsrc = g_wtlo + (size_t)n0 * N_DIM; local = idx - 1280; off = OFF_BLO; }
            int r = local >> 2, c = local & 3;
            cp_async16(bo + off + r * PITCH_B + c * 16,
                       gsrc + (size_t)r * N_DIM + k0 + c * 8);
        }
    };

    float acc[2][4][4];
    #pragma unroll
    for (int mi = 0; mi < 2; ++mi)
        #pragma unroll
        for (int nf = 0; nf < 4; ++nf)
            #pragma unroll
            for (int e = 0; e < 4; ++e) acc[mi][nf][e] = 0.f;

    load_tiles(0, 0);
    CP_COMMIT();
    CP_WAIT0();
    __syncthreads();

    const int NIT = N_DIM / 32;    // 64
    for (int it = 0; it < NIT; ++it) {
        const int buf = it & 1;
        const uint32_t bb = sb + buf * BUF_B;
        if (it + 1 < NIT) { load_tiles((it + 1) * 32, buf ^ 1); CP_COMMIT(); }

        #pragma unroll
        for (int ks = 0; ks < 2; ++ks) {
            uint32_t aHi[2][4], aLo[2][4], bHi[4][2], bLo[4][2];
            #pragma unroll
            for (int mi = 0; mi < 2; ++mi) {
                int row = wm * 32 + mi * 16 + lr + (lg & 1) * 8;
                int col = ks * 16 + (lg >> 1) * 8;
                uint32_t ad = bb + OFF_AHI + row * PITCH_B + col * 2;
                ldm_x4(aHi[mi][0], aHi[mi][1], aHi[mi][2], aHi[mi][3], ad);
                ldm_x4(aLo[mi][0], aLo[mi][1], aLo[mi][2], aLo[mi][3], ad + (OFF_ALO - OFF_AHI));
            }
            #pragma unroll
            for (int nj = 0; nj < 2; ++nj) {
                int row = wn * 32 + nj * 16 + (lg >> 1) * 8 + lr;
                int col = ks * 16 + (lg & 1) * 8;
                uint32_t bd = bb + OFF_BHI + row * PITCH_B + col * 2;
                uint32_t d0, d1, d2, d3;
                ldm_x4(d0, d1, d2, d3, bd);
                bHi[nj * 2][0] = d0; bHi[nj * 2][1] = d1;
                bHi[nj * 2 + 1][0] = d2; bHi[nj * 2 + 1][1] = d3;
                ldm_x4(d0, d1, d2, d3, bd + (OFF_BLO - OFF_BHI));
                bLo[nj * 2][0] = d0; bLo[nj * 2][1] = d1;
                bLo[nj * 2 + 1][0] = d2; bLo[nj * 2 + 1][1] = d3;
            }
            #pragma unroll
            for (int mi = 0; mi < 2; ++mi)
                #pragma unroll
                for (int nf = 0; nf < 4; ++nf) {
                    mma16816(acc[mi][nf], aHi[mi], bHi[nf]);
                    mma16816(acc[mi][nf], aHi[mi], bLo[nf]);
                    mma16816(acc[mi][nf], aLo[mi], bHi[nf]);
                }
        }

        CP_WAIT0();
        __syncthreads();
    }

    const int part  = n0 >> 11;
    const int h     = (n0 >> 7) & 15;
    const int dbase = n0 & 64;
    float* dstp = (part == 0 ? g_q : (part == 1 ? g_k : g_v))
                  + (size_t)h * (M_TOK * D_HEAD);

    #pragma unroll
    for (int mi = 0; mi < 2; ++mi)
        #pragma unroll
        for (int nf = 0; nf < 4; ++nf) {
            int row = m0 + wm * 32 + mi * 16 + (lane >> 2);
            int col = dbase + wn * 32 + nf * 8 + (lane & 3) * 2;
            *(float2*)(dstp + (size_t)row * D_HEAD + col) =
                make_float2(acc[mi][nf][0], acc[mi][nf][1]);
            *(float2*)(dstp + (size_t)(row + 8) * D_HEAD + col) =
                make_float2(acc[mi][nf][2], acc[mi][nf][3]);
        }
}

// ============================================================
// Kernel 2: build pre-split scatter-updated KV cache.
// Fresh K rows get fused RMS norm (one warp covers one 128-elem row).
// ============================================================
__global__ __launch_bounds__(256) void convert_kv_kernel(
    const float* __restrict__ cK, const float* __restrict__ cV,
    const int* __restrict__ Pp)
{
    const int P = Pp[0];
    int idx = blockIdx.x * 256 + threadIdx.x;      // float4 index over H*L*D
    int e = idx * 4;
    int d = e & 127;
    int l = (e >> 7) & (L_CACHE - 1);
    int h = e >> 19;
    size_t o = (size_t)h * (L_CACHE * D_HEAD) + (size_t)l * D_HEAD + d;
    bool fresh = (l >= P && l < P + M_TOK);        // warp-uniform (row-aligned)
    size_t of = ((size_t)h * M_TOK + (l - P)) * D_HEAD + d;

    float4 kv = fresh ? *(const float4*)(g_k + of) : *(const float4*)(cK + o);
    if (fresh) {
        float ss = kv.x * kv.x + kv.y * kv.y + kv.z * kv.z + kv.w * kv.w;
        #pragma unroll
        for (int off = 16; off > 0; off >>= 1)
            ss += __shfl_xor_sync(0xffffffffu, ss, off);
        float sc = rsqrtf(ss * (1.0f / 128.0f));
        kv.x *= sc; kv.y *= sc; kv.z *= sc; kv.w *= sc;
    }
    __nv_bfloat16 a0, b0, a1, b1, a2, b2, a3, b3;
    split_bf16(kv.x, a0, b0); split_bf16(kv.y, a1, b1);
    split_bf16(kv.z, a2, b2); split_bf16(kv.w, a3, b3);
    *(uint2*)(g_kchi + o) = make_uint2(pack2(a0, a1), pack2(a2, a3));
    *(uint2*)(g_kclo + o) = make_uint2(pack2(b0, b1), pack2(b2, b3));

    kv = fresh ? *(const float4*)(g_v + of) : *(const float4*)(cV + o);
    split_bf16(kv.x, a0, b0); split_bf16(kv.y, a1, b1);
    split_bf16(kv.z, a2, b2); split_bf16(kv.w, a3, b3);
    *(uint2*)(g_vchi + o) = make_uint2(pack2(a0, a1), pack2(a2, a3));
    *(uint2*)(g_vclo + o) = make_uint2(pack2(b0, b1), pack2(b2, b3));
}

// ============================================================
// Kernel 3: full-tensor attention (R15 config — best known).
// 8 warps = 8(m) x 1(l): warp owns 16 m-rows, full CL=64 l, full d=128.
// Register-P, cp.async double buffer, fused q RMS norm.
// grid (4, 16, 2), 256 threads, occ 1.
// ============================================================
#define CL        64
#define QP_B      272                        // 128 bf16 + 8 pad
#define Q_HI_OFF  0
#define Q_LO_OFF  (128 * QP_B)               // 34816
#define BUF0_OFF  (2 * 128 * QP_B)           // 69632
#define KB_KHI    0
#define KB_KLO    (CL * QP_B)                // 17408
#define KB_VHI    (2 * CL * QP_B)            // 34816
#define KB_VLO    (3 * CL * QP_B)            // 52224
#define KVBUF_B   (4 * CL * QP_B)            // 69632
#define ATTN_SMEM_B (BUF0_OFF + 2 * KVBUF_B) // 208896

__global__ __launch_bounds__(256, 1) void attn_kernel()
{
    extern __shared__ __align__(128) char sm[];
    const uint32_t sb = smem_u32(sm);

    const int t    = threadIdx.x;
    const int lane = t & 31;
    const int wid  = t >> 5;      // m-warp 0..7: rows wid*16..+16
    const int lr   = lane & 7;
    const int lg   = lane >> 3;
    const int h    = blockIdx.y;
    const int m0   = blockIdx.x * 128;
    const int z    = blockIdx.z;

    // ---- load Q tile with fused RMS norm (warp = row), split hi/lo ----
    const float* qbase = g_q + (h * M_TOK + m0) * D_HEAD;
    #pragma unroll
    for (int i = 0; i < 16; ++i) {
        int idx = t + i * 256;         // 0..4095 float4
        int row = idx >> 5;            // warp-uniform
        int c4  = idx & 31;            // = lane
        float4 v = *(const float4*)(qbase + row * 128 + c4 * 4);
        float ss = v.x * v.x + v.y * v.y + v.z * v.z + v.w * v.w;
        #pragma unroll
        for (int off = 16; off > 0; off >>= 1)
            ss += __shfl_xor_sync(0xffffffffu, ss, off);
        float sc = rsqrtf(ss * (1.0f / 128.0f));
        v.x *= sc; v.y *= sc; v.z *= sc; v.w *= sc;
        __nv_bfloat16 h0, l0, h1, l1, h2, l2, h3, l3;
        split_bf16(v.x, h0, l0); split_bf16(v.y, h1, l1);
        split_bf16(v.z, h2, l2); split_bf16(v.w, h3, l3);
        *(uint2*)(sm + Q_HI_OFF + row * QP_B + c4 * 8) = make_uint2(pack2(h0, h1), pack2(h2, h3));
        *(uint2*)(sm + Q_LO_OFF + row * QP_B + c4 * 8) = make_uint2(pack2(l0, l1), pack2(l2, l3));
    }

    const size_t hoff = (size_t)h * (L_CACHE * D_HEAD);

    auto load_chunk = [&](int ch, int buf) {
        const int l0g = z * 2048 + ch * CL;
        const char* srcs[4] = {
            (const char*)(g_kchi + hoff + (size_t)l0g * D_HEAD),
            (const char*)(g_kclo + hoff + (size_t)l0g * D_HEAD),
            (const char*)(g_vchi + hoff + (size_t)l0g * D_HEAD),
            (const char*)(g_vclo + hoff + (size_t)l0g * D_HEAD)
        };
        const uint32_t bo = sb + BUF0_OFF + buf * KVBUF_B;
        #pragma unroll
        for (int i = 0; i < 16; ++i) {
            int idx   = t + i * 256;
            int a     = idx >> 10;
            int local = idx & 1023;
            int row   = local >> 4;
            int c     = local & 15;
            cp_async16(bo + a * (CL * QP_B) + row * QP_B + c * 16,
                       srcs[a] + row * 256 + c * 16);
        }
    };

    // out accumulators: 16m x 128d per warp = 16(nd) x 4 = 64 regs
    float out_acc[16][4];
    #pragma unroll
    for (int nd = 0; nd < 16; ++nd)
        #pragma unroll
        for (int e = 0; e < 4; ++e) out_acc[nd][e] = 0.f;
    float den_acc[2] = {0.f, 0.f};

    load_chunk(0, 0);
    CP_COMMIT();
    CP_WAIT0();
    __syncthreads();

    const int NCH = 2048 / CL;   // 32
    for (int ch = 0; ch < NCH; ++ch) {
        const int buf = ch & 1;
        const uint32_t bo = sb + BUF0_OFF + buf * KVBUF_B;
        if (ch + 1 < NCH) { load_chunk(ch + 1, buf ^ 1); CP_COMMIT(); }

        // ---- S = Q K^T (warp: 16m x full 64l) -> s[8][4] ----
        float s[8][4];
        #pragma unroll
        for (int nj = 0; nj < 8; ++nj)
            #pragma unroll
            for (int e = 0; e < 4; ++e) s[nj][e] = 0.f;

        #pragma unroll
        for (int ks = 0; ks < 8; ++ks) {
            uint32_t aHi[4], aLo[4];
            {
                int row = wid * 16 + lr + (lg & 1) * 8;
                uint32_t ad = sb + Q_HI_OFF + row * QP_B + ks * 32 + (lg >> 1) * 16;
                ldm_x4(aHi[0], aHi[1], aHi[2], aHi[3], ad);
                ldm_x4(aLo[0], aLo[1], aLo[2], aLo[3], ad + Q_LO_OFF);
            }
            #pragma unroll
            for (int ng = 0; ng < 4; ++ng) {
                int row = ng * 16 + (lg >> 1) * 8 + lr;
                uint32_t bd = bo + KB_KHI + row * QP_B + ks * 32 + (lg & 1) * 16;
                uint32_t d0, d1, d2, d3, e0, e1, e2, e3;
                ldm_x4(d0, d1, d2, d3, bd);
                ldm_x4(e0, e1, e2, e3, bd + (KB_KLO - KB_KHI));
                uint32_t bh0[2] = {d0, d1}, bh1[2] = {d2, d3};
                uint32_t bl0[2] = {e0, e1}, bl1[2] = {e2, e3};
                mma16816(s[ng * 2],     aHi, bh0);
                mma16816(s[ng * 2],     aHi, bl0);
                mma16816(s[ng * 2],     aLo, bh0);
                mma16816(s[ng * 2 + 1], aHi, bh1);
                mma16816(s[ng * 2 + 1], aHi, bl1);
                mma16816(s[ng * 2 + 1], aLo, bh1);
            }
        }

        // ---- exp + den accumulation (registers only) ----
        {
            float sa = 0.f, sbv = 0.f;
            #pragma unroll
            for (int nj = 0; nj < 8; ++nj) {
                s[nj][0] = __expf(s[nj][0]);
                s[nj][1] = __expf(s[nj][1]);
                s[nj][2] = __expf(s[nj][2]);
                s[nj][3] = __expf(s[nj][3]);
                sa  += s[nj][0] + s[nj][1];
                sbv += s[nj][2] + s[nj][3];
            }
            den_acc[0] += sa;
            den_acc[1] += sbv;
        }

        // ---- repack S C-frags into PV A-frags (hi/lo), registers only ----
        uint32_t aPhi[4][4], aPlo[4][4];
        #pragma unroll
        for (int kp = 0; kp < 4; ++kp)
            #pragma unroll
            for (int half = 0; half < 2; ++half) {
                const float* sv = s[2 * kp + half];
                __nv_bfloat16 h0, l0b, h1, l1b;
                split_bf16(sv[0], h0, l0b); split_bf16(sv[1], h1, l1b);
                aPhi[kp][half * 2]     = pack2(h0, h1);
                aPlo[kp][half * 2]     = pack2(l0b, l1b);
                split_bf16(sv[2], h0, l0b); split_bf16(sv[3], h1, l1b);
                aPhi[kp][half * 2 + 1] = pack2(h0, h1);
                aPlo[kp][half * 2 + 1] = pack2(l0b, l1b);
            }

        // ---- out += P V (full 64l x 128d) ----
        #pragma unroll
        for (int kp = 0; kp < 4; ++kp) {
            #pragma unroll
            for (int g = 0; g < 8; ++g) {
                int vrow = kp * 16 + (lg & 1) * 8 + lr;
                int vcol = g * 16 + (lg >> 1) * 8;
                uint32_t bd = bo + KB_VHI + vrow * QP_B + vcol * 2;
                uint32_t d0, d1, d2, d3, e0, e1, e2, e3;
                ldm_x4_t(d0, d1, d2, d3, bd);
                ldm_x4_t(e0, e1, e2, e3, bd + (KB_VLO - KB_VHI));
                uint32_t bh0[2] = {d0, d1}, bh1[2] = {d2, d3};
                uint32_t bl0[2] = {e0, e1}, bl1[2] = {e2, e3};
                mma16816(out_acc[2 * g],     aPhi[kp], bh0);
                mma16816(out_acc[2 * g],     aPhi[kp], bl0);
                mma16816(out_acc[2 * g],     aPlo[kp], bh0);
                mma16816(out_acc[2 * g + 1], aPhi[kp], bh1);
                mma16816(out_acc[2 * g + 1], aPhi[kp], bl1);
                mma16816(out_acc[2 * g + 1], aPlo[kp], bh1);
            }
        }

        CP_WAIT0();
        __syncthreads();
    }

    // ---- denominator: shfl reduce, direct write (warp owns its 16 rows) ----
    float* pd = g_pd + (z * H_HEADS + h) * M_TOK + m0;
    #pragma unroll
    for (int half = 0; half < 2; ++half) {
        float v = den_acc[half];
        v += __shfl_xor_sync(0xffffffffu, v, 1);
        v += __shfl_xor_sync(0xffffffffu, v, 2);
        if ((lane & 3) == 0)
            pd[wid * 16 + half * 8 + (lane >> 2)] = v;
    }

    // ---- direct output write ----
    float* po = g_po + ((size_t)(z * H_HEADS + h) * M_TOK + m0) * D_HEAD;
    #pragma unroll
    for (int nd = 0; nd < 16; ++nd) {
        int row = wid * 16 + (lane >> 2);
        int col = nd * 8 + (lane & 3) * 2;
        *(float2*)(po + (size_t)row * D_HEAD + col) =
            make_float2(out_acc[nd][0], out_acc[nd][1]);
        *(float2*)(po + (size_t)(row + 8) * D_HEAD + col) =
            make_float2(out_acc[nd][2], out_acc[nd][3]);
    }
}

// ============================================================
// Kernel 4: combine L-splits and write output [M, H*D]
// ============================================================
__global__ __launch_bounds__(256) void combine_kernel(float* __restrict__ out)
{
    int idx = blockIdx.x * 256 + threadIdx.x;
    int e = idx * 4;
    int d = e & 127;
    int m = (e >> 7) & 511;
    int h = e >> 16;

    float4 a = *(const float4*)(g_po + e);
    float4 b = *(const float4*)(g_po + H_HEADS * M_TOK * D_HEAD + e);
    float dn = g_pd[h * M_TOK + m] + g_pd[H_HEADS * M_TOK + h * M_TOK + m];
    float inv = 1.0f / dn;
    float4 r = make_float4((a.x + b.x) * inv, (a.y + b.y) * inv,
                           (a.z + b.z) * inv, (a.w + b.w) * inv);
    *(float4*)(out + m * N_DIM + h * D_HEAD + d) = r;
}

// ============================================================
extern "C" void kernel_launch(void* const* d_in, const int* in_sizes, int n_in,
                              void* d_out, int out_size)
{
    const float* X  = (const float*)d_in[0];
    const float* W  = (const float*)d_in[1];
    const float* cK = (const float*)d_in[2];
    const float* cV = (const float*)d_in[3];
    const int*   Pp = (const int*)d_in[4];
    float* out = (float*)d_out;

    cudaFuncSetAttribute(attn_kernel,
                         cudaFuncAttributeMaxDynamicSharedMemorySize, ATTN_SMEM_B);
    cudaFuncSetAttribute(qkv_mma_kernel,
                         cudaFuncAttributeMaxDynamicSharedMemorySize, GEMM_SMEM);

    convert_xw_kernel<<<XW_XBLOCKS + (N3 / 32) * (N_DIM / 32), 256>>>(X, W);
    qkv_mma_kernel<<<dim3(N3 / 64, M_TOK / 128), 256, GEMM_SMEM>>>();
    convert_kv_kernel<<<(H_HEADS * L_CACHE * D_HEAD / 4) / 256, 256>>>(cK, cV, Pp);
    attn_kernel<<<dim3(M_TOK / 128, H_HEADS, 2), 256, ATTN_SMEM_B>>>();
    combine_kernel<<<(H_HEADS * M_TOK * D_HEAD / 4) / 256, 256>>>(out);
}